// round 16
// baseline (speedup 1.0000x reference)
#include <cuda_runtime.h>
#include <cuda_bf16.h>
#include <cstdint>

// LSTM rollout on mma.sync tf32 (m16n8k8), warp-staggered kc loop.
// lstm_mma: 128 CTAs x 512 thr (16 warps), 64 rows/CTA.
// warp = (Wl 0..7 col-group, mh 0..1 row-half). K-recur = 272 = 17 kc of 16.
// Stagger: kc rotated by 4*(Wg>>2) per warp; P order flipped for mh=1, so
// same-SMSP warps' load bursts overlap siblings' MMA bursts.

typedef unsigned u32;

__device__ u32   g_Wfrag[2 * 17 * 8 * 8 * 32 * 4];  // recurrent B frags (tf32)
__device__ u32   g_WXfrag[2 * 4 * 8 * 8 * 32 * 4];  // zx B frags (tf32)
__device__ float g_ZxA[(size_t)1 << 28];            // pass0 C-init frags
__device__ float g_ZxB[(size_t)1 << 28];            // pass1

__device__ __forceinline__ u32 tf32_(float f) {
    u32 r; asm("cvt.rna.tf32.f32 %0, %1;" : "=r"(r) : "f"(f)); return r;
}
__device__ __forceinline__ float fex2(float x) {
    float r; asm("ex2.approx.f32 %0, %1;" : "=f"(r) : "f"(x)); return r;
}
__device__ __forceinline__ float frcp(float x) {
    float r; asm("rcp.approx.f32 %0, %1;" : "=f"(r) : "f"(x));
    return fmaf(r, fmaf(-x, r, 1.0f), r);
}
__device__ __forceinline__ float sig_(float x) {
    x = fminf(30.f, fmaxf(-30.f, x));
    return frcp(1.0f + fex2(-1.4426950408889634f * x));
}
__device__ __forceinline__ float tanh_(float x) {
    x = fminf(30.f, fmaxf(-30.f, x));
    return fmaf(2.0f, frcp(1.0f + fex2(-2.8853900817779268f * x)), -1.0f);
}
__device__ __forceinline__ void mma_tf32(float* c, const u32* a, u32 b0, u32 b1) {
    asm volatile(
        "mma.sync.aligned.m16n8k8.row.col.f32.tf32.tf32.f32 "
        "{%0,%1,%2,%3}, {%4,%5,%6,%7}, {%8,%9}, {%0,%1,%2,%3};"
        : "+f"(c[0]), "+f"(c[1]), "+f"(c[2]), "+f"(c[3])
        : "r"(a[0]), "r"(a[1]), "r"(a[2]), "r"(a[3]), "r"(b0), "r"(b1));
}
__device__ __forceinline__ void pref_l2(const void* p) {
    asm volatile("prefetch.global.L2 [%0];" :: "l"(p));
}
// sigma on a 3-bit n index: n -> (n>>1) + 4*(n&1)
__device__ __forceinline__ int sig3(int n) { return (n >> 1) + 4 * (n & 1); }

// ---------------- presplat: weights -> tf32 B-fragment order ----------------
__global__ void presplat(const float* __restrict__ Wk, const float* __restrict__ Wr) {
    int idx = blockIdx.x * 256 + threadIdx.x;
    int L = idx & 31, nf = (idx >> 5) & 7, W = (idx >> 8) & 7;
    int T = L & 3;
    u32 d[4];
    if (idx < 2 * 17 * 8 * 8 * 32) {
        int rem = idx >> 11, kc = rem % 17, P = rem / 17;
        int u = P * 128 + W * 16 + (nf >> 2) * 8 + sig3(L >> 2);
        int col = (nf & 3) * 256 + u;
#pragma unroll
        for (int e = 0; e < 4; ++e) {
            int kg = kc * 16 + T + 4 * e;
            float v = (kg < 16) ? Wk[(64 + kg) * 1024 + col]
                                : Wr[(kg - 16) * 1024 + col];
            d[e] = tf32_(v);
        }
        *(uint4*)(g_Wfrag + (size_t)idx * 4) = make_uint4(d[0], d[1], d[2], d[3]);
    } else {
        int idx2 = idx - 2 * 17 * 8 * 8 * 32;
        if (idx2 >= 2 * 4 * 8 * 8 * 32) return;
        L = idx2 & 31; nf = (idx2 >> 5) & 7; W = (idx2 >> 8) & 7;
        T = L & 3;
        int kc = (idx2 >> 11) & 3, P = idx2 >> 13;
        int u = P * 128 + W * 16 + (nf >> 2) * 8 + sig3(L >> 2);
        int col = (nf & 3) * 256 + u;
#pragma unroll
        for (int e = 0; e < 4; ++e)
            d[e] = tf32_(Wk[(kc * 16 + T + 4 * e) * 1024 + col]);
        *(uint4*)(g_WXfrag + (size_t)idx2 * 4) = make_uint4(d[0], d[1], d[2], d[3]);
    }
}

// ---------------- zx_gemm: Zx = x @ Wk[0:64] + bias (tf32) ----------------
__global__ void __launch_bounds__(256, 1)
zx_gemm(const float* __restrict__ x, const float* __restrict__ bias)
{
    __shared__ u32 Ax[4096];           // 4kc x 2s x 4mf x 32L x 4comp
    const int tid = threadIdx.x, W = tid >> 5, L = tid & 31;
    const int b0 = blockIdx.x * 64;

    float biasr[2][8][2];
#pragma unroll
    for (int P = 0; P < 2; ++P)
#pragma unroll
        for (int nf = 0; nf < 8; ++nf)
#pragma unroll
            for (int cc = 0; cc < 2; ++cc)
                biasr[P][nf][cc] = bias[(nf & 3) * 256 + P * 128 + W * 16
                                        + (nf >> 2) * 8 + (L & 3) + 4 * cc];

    for (int t = 0; t < 64; ++t) {
#pragma unroll
        for (int i = 0; i < 4; ++i) {
            int q4 = tid + i * 256;
            int r = q4 >> 4, fb = (q4 & 15) * 4;
            const float* xp = x + ((size_t)(b0 + r) * 64 + t) * 64 + fb;
            float4 v = *(const float4*)xp;
            if (t < 63) pref_l2(xp + 64);
            float va[4] = {v.x, v.y, v.z, v.w};
#pragma unroll
            for (int e = 0; e < 4; ++e) {
                int k = fb + e;
                int kc = k >> 4, s = (k >> 3) & 1, p = k & 7, T = p & 3;
                int cell = ((kc * 2 + s) * 4 + (r >> 4)) * 32 + (r & 7) * 4 + T;
                int comp = ((r >> 3) & 1) + ((p >= 4) ? 2 : 0);
                Ax[cell * 4 + comp] = tf32_(va[e]);
            }
        }
        __syncthreads();

#pragma unroll
        for (int P = 0; P < 2; ++P) {
            float C[4][8][4];
#pragma unroll
            for (int mf = 0; mf < 4; ++mf)
#pragma unroll
                for (int nf = 0; nf < 8; ++nf) {
                    C[mf][nf][0] = biasr[P][nf][0];
                    C[mf][nf][1] = biasr[P][nf][1];
                    C[mf][nf][2] = biasr[P][nf][0];
                    C[mf][nf][3] = biasr[P][nf][1];
                }
#pragma unroll
            for (int kc = 0; kc < 4; ++kc) {
                uint4 a[4][2];
#pragma unroll
                for (int mf = 0; mf < 4; ++mf)
#pragma unroll
                    for (int s = 0; s < 2; ++s)
                        a[mf][s] = *(const uint4*)(Ax
                            + (((kc * 2 + s) * 4 + mf) * 32 + L) * 4);
#pragma unroll
                for (int half = 0; half < 2; ++half) {
                    uint4 Bq[4];
#pragma unroll
                    for (int n4 = 0; n4 < 4; ++n4)
                        Bq[n4] = *(const uint4*)(g_WXfrag
                            + ((size_t)(((P * 4 + kc) * 8 + W) * 8 + half * 4 + n4) * 32 + L) * 4);
#pragma unroll
                    for (int mf = 0; mf < 4; ++mf)
#pragma unroll
                        for (int n4 = 0; n4 < 4; ++n4) {
                            mma_tf32(C[mf][half * 4 + n4], (const u32*)&a[mf][0],
                                     Bq[n4].x, Bq[n4].y);
                            mma_tf32(C[mf][half * 4 + n4], (const u32*)&a[mf][1],
                                     Bq[n4].z, Bq[n4].w);
                        }
                }
            }
            float* zx = P ? g_ZxB : g_ZxA;
            size_t ct = (size_t)b0 + t;
#pragma unroll
            for (int mf = 0; mf < 4; ++mf)
#pragma unroll
                for (int nf = 0; nf < 8; ++nf)
                    *(float4*)(zx + ((((ct * 8 + W) * 4 + mf) * 8 + nf) * 32 + L) * 4)
                        = *(float4*)C[mf][nf];
        }
        __syncthreads();
    }
}

// ---------------- recurrent rollout on tf32 mma (512 thr, staggered) -------
#define AHW2 (17 * 2 * 4 * 32 * 4)   // 17408 u32 per parity

__global__ void __launch_bounds__(512, 1)
lstm_mma(const float* __restrict__ y0, const float* __restrict__ dw,
         const float* __restrict__ db, float* __restrict__ out)
{
    extern __shared__ u32 smu[];
    u32* Asm   = smu;                         // [2][AHW2]
    u32* Cst   = smu + 2 * AHW2;              // [32][512] c-state (float bits)
    float* yring = (float*)(Cst + 32 * 512);  // [16][64]
    float* redW  = yring + 16 * 64;           // [8][64]

    const int tid = threadIdx.x, L = tid & 31;
    const int Wg = tid >> 5;
    const int Wl = Wg & 7;                    // col-group
    const int mh = Wg >> 3;                   // row-half (mf = 2mh+i)
    const int roff = (Wg >> 2) * 4;           // kc rotation: distinct per SMSP-mate
    const int b0 = blockIdx.x * 64;

    for (int i = tid; i < 2 * AHW2; i += 512) Asm[i] = 0u;
    for (int i = tid; i < 32 * 512; i += 512) Cst[i] = 0u;
    for (int i = tid; i < 1024; i += 512) {
        int j = i >> 6, r = i & 63;
        yring[(15 - j) * 64 + r] = y0[(size_t)(b0 + r) * 16 + j];
    }

    float dwr[2][4];
#pragma unroll
    for (int P = 0; P < 2; ++P)
#pragma unroll
        for (int e = 0; e < 4; ++e) {
            int uh = e >> 1, cc = e & 1;
            dwr[P][e] = dw[P * 128 + Wl * 16 + uh * 8 + (L & 3) + 4 * cc];
        }
    const float db0 = db[0];
    __syncthreads();

    // yp k-chunk (kc=0): scattered tf32 stores (2 values/thread)
    auto buildYp = [&](int par, int tt) {
        int r = tid & 63, jp = tid >> 6;
#pragma unroll
        for (int q = 0; q < 2; ++q) {
            int j = jp * 2 + q;
            float v = yring[((tt - 1 - j) & 15) * 64 + r];
            int s = j >> 3, p = j & 7, T = p & 3;
            int cell = ((s) * 4 + (r >> 4)) * 32 + (r & 7) * 4 + T;   // kc = 0
            int comp = ((r >> 3) & 1) + ((p >= 4) ? 2 : 0);
            Asm[par * AHW2 + cell * 4 + comp] = tf32_(v);
        }
    };
    buildYp(0, 0);
    __syncthreads();

    for (int t = 0; t < 64; ++t) {
        const int cur = t & 1, nxt = cur ^ 1;
        float part[4];
#pragma unroll
        for (int e = 0; e < 4; ++e) part[e] = 0.f;

#pragma unroll
        for (int pp = 0; pp < 2; ++pp) {
            const int P = mh ? (1 - pp) : pp;   // P-order flipped for mh=1
            float C[2][8][4];
            const float* zx = P ? g_ZxB : g_ZxA;
            size_t ct = (size_t)b0 + t;
#pragma unroll
            for (int i = 0; i < 2; ++i) {
                int mf = 2 * mh + i;
#pragma unroll
                for (int nf = 0; nf < 8; ++nf) {
                    const float* zp = zx
                        + ((((ct * 8 + Wl) * 4 + mf) * 8 + nf) * 32 + L) * 4;
                    *(float4*)C[i][nf] = *(const float4*)zp;
                    if (t < 63) pref_l2(zp + 32768);  // ct stride = 8*4*8*32*4
                }
            }

#pragma unroll 1
            for (int kc = 0; kc < 17; ++kc) {
                int kcr = kc + roff;
                if (kcr >= 17) kcr -= 17;       // rotated kc (C accum order-free)
                uint4 a[2][2];
#pragma unroll
                for (int i = 0; i < 2; ++i)
#pragma unroll
                    for (int s = 0; s < 2; ++s)
                        a[i][s] = *(const uint4*)(Asm + cur * AHW2
                            + (((kcr * 2 + s) * 4 + (2 * mh + i)) * 32 + L) * 4);
#pragma unroll
                for (int half = 0; half < 2; ++half) {
                    uint4 Bq[4];
#pragma unroll
                    for (int n4 = 0; n4 < 4; ++n4)
                        Bq[n4] = *(const uint4*)(g_Wfrag
                            + ((size_t)(((P * 17 + kcr) * 8 + Wl) * 8 + half * 4 + n4) * 32 + L) * 4);
#pragma unroll
                    for (int i = 0; i < 2; ++i)
#pragma unroll
                        for (int n4 = 0; n4 < 4; ++n4) {
                            mma_tf32(C[i][half * 4 + n4], (const u32*)&a[i][0],
                                     Bq[n4].x, Bq[n4].y);
                            mma_tf32(C[i][half * 4 + n4], (const u32*)&a[i][1],
                                     Bq[n4].z, Bq[n4].w);
                        }
                }
            }

            // gates + h write: unit u = P*128+Wl*16+uh*8+(L&3)+4cc (sigma applied)
            const int kcA = 1 + P * 8 + Wl;
#pragma unroll
            for (int i = 0; i < 2; ++i) {
                int mf = 2 * mh + i;
#pragma unroll
                for (int uh = 0; uh < 2; ++uh) {
                    u32 q[4];
#pragma unroll
                    for (int jr = 0; jr < 2; ++jr)
#pragma unroll
                        for (int cc = 0; cc < 2; ++cc) {
                            float zi = C[i][uh * 4 + 0][jr * 2 + cc];
                            float zf = C[i][uh * 4 + 1][jr * 2 + cc];
                            float zg = C[i][uh * 4 + 2][jr * 2 + cc];
                            float zo = C[i][uh * 4 + 3][jr * 2 + cc];
                            int e = (((P * 2 + i) * 2 + uh) * 2 + jr) * 2 + cc;
                            float co = __uint_as_float(Cst[e * 512 + tid]);
                            float cn = sig_(zf) * co + sig_(zi) * tanh_(zg);
                            float h = sig_(zo) * tanh_(cn);
                            Cst[e * 512 + tid] = __float_as_uint(cn);
                            q[jr + 2 * cc] = tf32_(h);
                            part[i * 2 + jr] += h * dwr[P][uh * 2 + cc];
                        }
                    *(uint4*)(Asm + nxt * AHW2
                        + (((kcA * 2 + uh) * 4 + mf) * 32 + L) * 4)
                        = make_uint4(q[0], q[1], q[2], q[3]);
                }
            }
        }

        // reduce over 4-lane unit groups, slot per (Wl, row)
#pragma unroll
        for (int e = 0; e < 4; ++e) {
            float v = part[e];
            v += __shfl_xor_sync(0xffffffffu, v, 1);
            v += __shfl_xor_sync(0xffffffffu, v, 2);
            if ((L & 3) == 0) {
                int i = e >> 1, jr = e & 1;
                int row = (2 * mh + i) * 16 + (L >> 2) + jr * 8;
                redW[Wl * 64 + row] = v;
            }
        }
        __syncthreads();

        if (tid < 64) {
            float pred = db0;
#pragma unroll
            for (int w = 0; w < 8; ++w) pred += redW[w * 64 + tid];
            out[(size_t)(b0 + tid) * 64 + t] = pred;
            yring[(t & 15) * 64 + tid] = pred;
        }
        __syncthreads();
        if (t < 63) {
            buildYp(nxt, t + 1);
            __syncthreads();
        }
    }
}

extern "C" void kernel_launch(void* const* d_in, const int* in_sizes, int n_in,
                              void* d_out, int out_size) {
    const float* x    = (const float*)d_in[0];
    const float* y0   = (const float*)d_in[1];
    const float* Wk   = (const float*)d_in[2];
    const float* Wr   = (const float*)d_in[3];
    const float* bias = (const float*)d_in[4];
    const float* dw   = (const float*)d_in[5];
    const float* db   = (const float*)d_in[6];
    float* out = (float*)d_out;

    const int smem_bytes = (2 * AHW2 + 32 * 512) * 4 + (16 * 64 + 8 * 64) * 4;
    static int done = 0;
    if (!done) {
        cudaFuncSetAttribute(lstm_mma,
                             cudaFuncAttributeMaxDynamicSharedMemorySize, smem_bytes);
        done = 1;
    }
    presplat<<<336, 256>>>(Wk, Wr);
    zx_gemm<<<128, 256>>>(x, bias);
    lstm_mma<<<128, 512, smem_bytes>>>(y0, dw, db, out);
}

// round 17
// speedup vs baseline: 1.4906x; 1.4906x over previous
#include <cuda_runtime.h>
#include <cuda_fp16.h>
#include <cstdint>

// LSTM rollout on mma.sync fp16 m16n8k16 single-path (f32 accum).
// fp16 mantissa == tf32 mantissa (10 bits) -> same precision, half the MMAs.
// lstm_mma: 128 CTAs x 512 thr (16 warps), 64 rows/CTA.
// warp = (Wl 0..7 col-group, mh 0..1 row-half). K-recur = 272 = 17 kc of 16.

typedef unsigned u32;

__device__ u32   g_Wfrag[2 * 17 * 8 * 8 * 32 * 2];  // recurrent B frags (fp16)
__device__ u32   g_WXfrag[2 * 4 * 8 * 8 * 32 * 2];  // zx B frags (fp16)
__device__ float g_ZxA[(size_t)1 << 28];            // pass0 C-init frags
__device__ float g_ZxB[(size_t)1 << 28];            // pass1

__device__ __forceinline__ u32 packh(float a, float b) {
    __half2 t = __floats2half2_rn(a, b);
    return *reinterpret_cast<u32*>(&t);
}
__device__ __forceinline__ float fex2(float x) {
    float r; asm("ex2.approx.f32 %0, %1;" : "=f"(r) : "f"(x)); return r;
}
__device__ __forceinline__ float frcp(float x) {
    float r; asm("rcp.approx.f32 %0, %1;" : "=f"(r) : "f"(x));
    return fmaf(r, fmaf(-x, r, 1.0f), r);
}
__device__ __forceinline__ float sig_(float x) {
    x = fminf(30.f, fmaxf(-30.f, x));
    return frcp(1.0f + fex2(-1.4426950408889634f * x));
}
__device__ __forceinline__ float tanh_(float x) {
    x = fminf(30.f, fmaxf(-30.f, x));
    return fmaf(2.0f, frcp(1.0f + fex2(-2.8853900817779268f * x)), -1.0f);
}
__device__ __forceinline__ void mma_f16(float* c, const u32* a, u32 b0, u32 b1) {
    asm volatile(
        "mma.sync.aligned.m16n8k16.row.col.f32.f16.f16.f32 "
        "{%0,%1,%2,%3}, {%4,%5,%6,%7}, {%8,%9}, {%0,%1,%2,%3};"
        : "+f"(c[0]), "+f"(c[1]), "+f"(c[2]), "+f"(c[3])
        : "r"(a[0]), "r"(a[1]), "r"(a[2]), "r"(a[3]), "r"(b0), "r"(b1));
}
__device__ __forceinline__ void pref_l2(const void* p) {
    asm volatile("prefetch.global.L2 [%0];" :: "l"(p));
}

// ---------------- presplat: weights -> fp16 B-fragment order ----------------
// cell (P,kc,W,nf,L): k0 = kc*16+(L&3)*2; n-col q = L>>2:
//   u = P*128+W*16+(nf>>2)*8+q; col = (nf&3)*256+u
// uint2 = {b(k0,k0+1), b(k0+8,k0+9)}
__global__ void presplat(const float* __restrict__ Wk, const float* __restrict__ Wr) {
    int idx = blockIdx.x * 256 + threadIdx.x;
    int L = idx & 31, nf = (idx >> 5) & 7, W = (idx >> 8) & 7;
    float v[4];
    if (idx < 2 * 17 * 8 * 8 * 32) {
        int rem = idx >> 11, kc = rem % 17, P = rem / 17;
        int u = P * 128 + W * 16 + (nf >> 2) * 8 + (L >> 2);
        int col = (nf & 3) * 256 + u;
        int k0 = kc * 16 + (L & 3) * 2;
#pragma unroll
        for (int e = 0; e < 4; ++e) {
            int kg = k0 + (e >> 1) * 8 + (e & 1);
            v[e] = (kg < 16) ? Wk[(64 + kg) * 1024 + col]
                             : Wr[(kg - 16) * 1024 + col];
        }
        u32* d = g_Wfrag + (size_t)idx * 2;
        d[0] = packh(v[0], v[1]);
        d[1] = packh(v[2], v[3]);
    } else {
        int idx2 = idx - 2 * 17 * 8 * 8 * 32;
        if (idx2 >= 2 * 4 * 8 * 8 * 32) return;
        L = idx2 & 31; nf = (idx2 >> 5) & 7; W = (idx2 >> 8) & 7;
        int kc = (idx2 >> 11) & 3, P = idx2 >> 13;
        int u = P * 128 + W * 16 + (nf >> 2) * 8 + (L >> 2);
        int col = (nf & 3) * 256 + u;
        int k0 = kc * 16 + (L & 3) * 2;
#pragma unroll
        for (int e = 0; e < 4; ++e)
            v[e] = Wk[(k0 + (e >> 1) * 8 + (e & 1)) * 1024 + col];
        u32* d = g_WXfrag + (size_t)idx2 * 2;
        d[0] = packh(v[0], v[1]);
        d[1] = packh(v[2], v[3]);
    }
}

// ---------------- zx_gemm: Zx = x @ Wk[0:64] + bias (fp16) ----------------
__global__ void __launch_bounds__(256, 1)
zx_gemm(const float* __restrict__ x, const float* __restrict__ bias)
{
    __shared__ u32 Ax[4 * 4 * 32 * 4];   // [kc][mf][L][4comp] fp16x2
    const int tid = threadIdx.x, W = tid >> 5, L = tid & 31;
    const int b0 = blockIdx.x * 64;

    float biasr[2][8][2];
#pragma unroll
    for (int P = 0; P < 2; ++P)
#pragma unroll
        for (int nf = 0; nf < 8; ++nf)
#pragma unroll
            for (int cc = 0; cc < 2; ++cc)
                biasr[P][nf][cc] = bias[(nf & 3) * 256 + P * 128 + W * 16
                                        + (nf >> 2) * 8 + (L & 3) * 2 + cc];

    for (int t = 0; t < 64; ++t) {
#pragma unroll
        for (int i = 0; i < 4; ++i) {
            int q4 = tid + i * 256;
            int r = q4 >> 4, fb = (q4 & 15) * 4;
            const float* xp = x + ((size_t)(b0 + r) * 64 + t) * 64 + fb;
            float4 v = *(const float4*)xp;
            if (t < 63) pref_l2(xp + 64);
            float va[4] = {v.x, v.y, v.z, v.w};
#pragma unroll
            for (int p2 = 0; p2 < 2; ++p2) {
                int f0 = fb + p2 * 2;
                int kin = f0 & 15, kc = f0 >> 4;
                int Lw = (r & 7) * 4 + ((kin & 7) >> 1);
                int mf = r >> 4;
                int j = (((r & 15) >= 8) ? 1 : 0) + ((kin >= 8) ? 2 : 0);
                Ax[((kc * 4 + mf) * 32 + Lw) * 4 + j] = packh(va[p2 * 2], va[p2 * 2 + 1]);
            }
        }
        __syncthreads();

#pragma unroll
        for (int P = 0; P < 2; ++P) {
            float C[4][8][4];
#pragma unroll
            for (int mf = 0; mf < 4; ++mf)
#pragma unroll
                for (int nf = 0; nf < 8; ++nf) {
                    C[mf][nf][0] = biasr[P][nf][0];
                    C[mf][nf][1] = biasr[P][nf][1];
                    C[mf][nf][2] = biasr[P][nf][0];
                    C[mf][nf][3] = biasr[P][nf][1];
                }
#pragma unroll
            for (int kc = 0; kc < 4; ++kc) {
                uint2 Bq[8];
#pragma unroll
                for (int nf = 0; nf < 8; ++nf)
                    Bq[nf] = *(const uint2*)(g_WXfrag
                        + ((size_t)(((P * 4 + kc) * 8 + W) * 8 + nf) * 32 + L) * 2);
#pragma unroll
                for (int mf = 0; mf < 4; ++mf) {
                    uint4 a = *(const uint4*)(Ax + ((kc * 4 + mf) * 32 + L) * 4);
#pragma unroll
                    for (int nf = 0; nf < 8; ++nf)
                        mma_f16(C[mf][nf], (const u32*)&a, Bq[nf].x, Bq[nf].y);
                }
            }
            float* zx = P ? g_ZxB : g_ZxA;
            size_t ct = (size_t)b0 + t;
#pragma unroll
            for (int mf = 0; mf < 4; ++mf)
#pragma unroll
                for (int nf = 0; nf < 8; ++nf)
                    *(float4*)(zx + ((((ct * 8 + W) * 4 + mf) * 8 + nf) * 32 + L) * 4)
                        = *(float4*)C[mf][nf];
        }
        __syncthreads();
    }
}

// ---------------- recurrent rollout on fp16 mma (512 thr) ------------------
#define AHW (17 * 4 * 32 * 4)   // 8704 u32 per parity (fp16x2 A frags)

__global__ void __launch_bounds__(512, 1)
lstm_mma(const float* __restrict__ y0, const float* __restrict__ dw,
         const float* __restrict__ db, float* __restrict__ out)
{
    extern __shared__ u32 smu[];
    u32* Asm   = smu;                         // [2][AHW]
    u32* Cst   = smu + 2 * AHW;               // [32][512] c-state (float bits)
    float* yring = (float*)(Cst + 32 * 512);  // [16][64]
    float* redW  = yring + 16 * 64;           // [8][64]

    const int tid = threadIdx.x, L = tid & 31;
    const int Wg = tid >> 5;
    const int Wl = Wg & 7;                    // col-group
    const int mh = Wg >> 3;                   // row-half (mf = 2mh+i)
    const int b0 = blockIdx.x * 64;

    for (int i = tid; i < 2 * AHW; i += 512) Asm[i] = 0u;
    for (int i = tid; i < 32 * 512; i += 512) Cst[i] = 0u;
    for (int i = tid; i < 1024; i += 512) {
        int j = i >> 6, r = i & 63;
        yring[(15 - j) * 64 + r] = y0[(size_t)(b0 + r) * 16 + j];
    }

    float dwr[2][4];
#pragma unroll
    for (int P = 0; P < 2; ++P)
#pragma unroll
        for (int e = 0; e < 4; ++e)
            dwr[P][e] = dw[P * 128 + Wl * 16 + (e >> 1) * 8 + (L & 3) * 2 + (e & 1)];
    const float db0 = db[0];
    __syncthreads();

    // yp k-chunk (kc=0) fragments for step tt into parity par
    auto buildYp = [&](int par, int tt) {
        int r = tid & 63, jp = tid >> 6, j0 = jp * 2;
        float v0 = yring[((tt - 1 - j0) & 15) * 64 + r];
        float v1 = yring[((tt - 2 - j0) & 15) * 64 + r];
        int mf = r >> 4;
        int Lw = (r & 7) * 4 + ((j0 & 7) >> 1);
        int j = (((r & 15) >= 8) ? 1 : 0) + ((j0 >= 8) ? 2 : 0);
        Asm[par * AHW + (mf * 32 + Lw) * 4 + j] = packh(v0, v1);
    };
    buildYp(0, 0);
    __syncthreads();

    for (int t = 0; t < 64; ++t) {
        const int cur = t & 1, nxt = cur ^ 1;
        float part[4];
#pragma unroll
        for (int e = 0; e < 4; ++e) part[e] = 0.f;

#pragma unroll
        for (int P = 0; P < 2; ++P) {
            float C[2][8][4];
            const float* zx = P ? g_ZxB : g_ZxA;
            size_t ct = (size_t)b0 + t;
#pragma unroll
            for (int i = 0; i < 2; ++i) {
                int mf = 2 * mh + i;
#pragma unroll
                for (int nf = 0; nf < 8; ++nf) {
                    const float* zp = zx
                        + ((((ct * 8 + Wl) * 4 + mf) * 8 + nf) * 32 + L) * 4;
                    *(float4*)C[i][nf] = *(const float4*)zp;
                    if (t < 63) pref_l2(zp + 32768);  // ct stride
                }
            }

#pragma unroll 1
            for (int kc = 0; kc < 17; ++kc) {
                uint4 a[2];
#pragma unroll
                for (int i = 0; i < 2; ++i)
                    a[i] = *(const uint4*)(Asm + cur * AHW
                        + ((kc * 4 + (2 * mh + i)) * 32 + L) * 4);
                uint2 Bq[8];
#pragma unroll
                for (int nf = 0; nf < 8; ++nf)
                    Bq[nf] = *(const uint2*)(g_Wfrag
                        + ((size_t)(((P * 17 + kc) * 8 + Wl) * 8 + nf) * 32 + L) * 2);
#pragma unroll
                for (int i = 0; i < 2; ++i)
#pragma unroll
                    for (int nf = 0; nf < 8; ++nf)
                        mma_f16(C[i][nf], (const u32*)&a[i], Bq[nf].x, Bq[nf].y);
            }

            // gates + h write: unit u = P*128+Wl*16+uh*8+(L&3)*2+cc
            const int kcA = 1 + P * 8 + Wl;
#pragma unroll
            for (int i = 0; i < 2; ++i) {
                int mf = 2 * mh + i;
                float hv[2][2][2];
#pragma unroll
                for (int uh = 0; uh < 2; ++uh)
#pragma unroll
                    for (int jr = 0; jr < 2; ++jr)
#pragma unroll
                        for (int cc = 0; cc < 2; ++cc) {
                            float zi = C[i][uh * 4 + 0][jr * 2 + cc];
                            float zf = C[i][uh * 4 + 1][jr * 2 + cc];
                            float zg = C[i][uh * 4 + 2][jr * 2 + cc];
                            float zo = C[i][uh * 4 + 3][jr * 2 + cc];
                            int e = (((P * 2 + i) * 2 + uh) * 2 + jr) * 2 + cc;
                            float co = __uint_as_float(Cst[e * 512 + tid]);
                            float cn = sig_(zf) * co + sig_(zi) * tanh_(zg);
                            float h = sig_(zo) * tanh_(cn);
                            Cst[e * 512 + tid] = __float_as_uint(cn);
                            hv[uh][jr][cc] = h;
                            part[i * 2 + jr] += h * dwr[P][uh * 2 + cc];
                        }
                u32 hh[4];
#pragma unroll
                for (int uh = 0; uh < 2; ++uh)
#pragma unroll
                    for (int jr = 0; jr < 2; ++jr)
                        hh[jr + 2 * uh] = packh(hv[uh][jr][0], hv[uh][jr][1]);
                *(uint4*)(Asm + nxt * AHW + ((kcA * 4 + mf) * 32 + L) * 4)
                    = make_uint4(hh[0], hh[1], hh[2], hh[3]);
            }
        }

        // reduce over 4-lane unit groups, slot per (Wl, row)
#pragma unroll
        for (int e = 0; e < 4; ++e) {
            float v = part[e];
            v += __shfl_xor_sync(0xffffffffu, v, 1);
            v += __shfl_xor_sync(0xffffffffu, v, 2);
            if ((L & 3) == 0) {
                int i = e >> 1, jr = e & 1;
                int row = (2 * mh + i) * 16 + (L >> 2) + jr * 8;
                redW[Wl * 64 + row] = v;
            }
        }
        __syncthreads();

        if (tid < 64) {
            float pred = db0;
#pragma unroll
            for (int w = 0; w < 8; ++w) pred += redW[w * 64 + tid];
            out[(size_t)(b0 + tid) * 64 + t] = pred;
            yring[(t & 15) * 64 + tid] = pred;
        }
        __syncthreads();
        if (t < 63) {
            buildYp(nxt, t + 1);
            __syncthreads();
        }
    }
}

extern "C" void kernel_launch(void* const* d_in, const int* in_sizes, int n_in,
                              void* d_out, int out_size) {
    const float* x    = (const float*)d_in[0];
    const float* y0   = (const float*)d_in[1];
    const float* Wk   = (const float*)d_in[2];
    const float* Wr   = (const float*)d_in[3];
    const float* bias = (const float*)d_in[4];
    const float* dw   = (const float*)d_in[5];
    const float* db   = (const float*)d_in[6];
    float* out = (float*)d_out;

    const int smem_bytes = (2 * AHW + 32 * 512) * 4 + (16 * 64 + 8 * 64) * 4;
    static int done = 0;
    if (!done) {
        cudaFuncSetAttribute(lstm_mma,
                             cudaFuncAttributeMaxDynamicSharedMemorySize, smem_bytes);
        done = 1;
    }
    presplat<<<336, 256>>>(Wk, Wr);
    zx_gemm<<<128, 256>>>(x, bias);
    lstm_mma<<<128, 512, smem_bytes>>>(y0, dw, db, out);
}